// round 5
// baseline (speedup 1.0000x reference)
#include <cuda_runtime.h>
#include <cuda_bf16.h>
#include <mma.h>
#include <cstdint>

using namespace nvcuda;

// Problem constants
#define NN   50000
#define EE   1600000
#define BB   128
#define MM   64
#define HH   32
#define FINF 20
#define KF   44            // folded K: [x(16), x*f(16), de(4), rows*f(4), cols*f(4)]
#define NCOL 2048          // M*H output columns
#define NT   128           // nodes per CTA tile
#define TILES 391          // ceil(50000/128) -> 50048 padded rows
#define NROWS_PAD (TILES * NT)
#define ROWW 96            // bf16 per packed row: [hi 0..47 | lo 48..95], 48-padded
#define SMSTRIDE 112       // smem row stride in bf16 (mult of 8, 224B)

// ---------------- device scratch ----------------
__device__ float4 g_rows[NN];
__device__ float4 g_cols[NN];
__device__ int   g_diag[NN];
__device__ int   g_end[BB];
__device__ float g_nn[BB];
__device__ float g_sdp[BB * FINF];
__device__ float g_sa[BB * FINF];
__device__ __nv_bfloat16 g_A2[(size_t)NROWS_PAD * ROWW];  // packed hi/lo features
__device__ __nv_bfloat16 g_W2[(size_t)NCOL * ROWW];       // packed hi/lo weights
__device__ float g_c[BB * NCOL];      // per-graph constant (basis 1,4 + bias)
__device__ float g_inv[BB * NCOL];    // per-graph accumulated relu sums

// ---------------- K0: zero scratch ----------------
__global__ void k_zero() {
    int i = blockIdx.x * blockDim.x + threadIdx.x;
    int stride = gridDim.x * blockDim.x;
    float4 z4 = make_float4(0.f, 0.f, 0.f, 0.f);
    for (int j = i; j < NN; j += stride) { g_rows[j] = z4; g_cols[j] = z4; g_diag[j] = -1; }
    for (int j = i; j < BB * FINF; j += stride) { g_sdp[j] = 0.f; g_sa[j] = 0.f; }
    for (int j = i; j < BB * NCOL; j += stride) g_inv[j] = 0.f;
    const int padN = (NROWS_PAD - NN) * ROWW;
    __nv_bfloat16 zb = __float2bfloat16(0.f);
    for (int j = i; j < padN; j += stride) g_A2[(size_t)NN * ROWW + j] = zb;
}

// ---------------- K1: segment boundaries + counts ----------------
__global__ void k_bound(const int* __restrict__ batch) {
    int n = blockIdx.x * blockDim.x + threadIdx.x;
    if (n >= NN) return;
    int b = batch[n];
    int nb = (n + 1 < NN) ? batch[n + 1] : BB;
    if (nb != b) g_end[b] = n + 1;
}
__global__ void k_counts() {
    int b = threadIdx.x;
    if (b < BB) {
        int s = (b == 0) ? 0 : g_end[b - 1];
        g_nn[b] = (float)(g_end[b] - s);
    }
}

// ---------------- K2: edge pass ----------------
__global__ void k_edge(const int* __restrict__ ei, const float4* __restrict__ attr) {
    int e = blockIdx.x * blockDim.x + threadIdx.x;
    if (e >= EE) return;
    int s = __ldg(&ei[e]);
    int d = __ldg(&ei[EE + e]);
    float4 a = attr[e];
    atomicAdd(&g_rows[s], a);
    atomicAdd(&g_cols[d], a);
    if (s == d) atomicMax(&g_diag[s], e);
}

// ---------------- K3: packed bf16 hi/lo features + per-graph sums ----------------
__global__ void __launch_bounds__(256) k_node(const float4* __restrict__ x4,
                                              const float4* __restrict__ attr,
                                              const int* __restrict__ batch) {
    __shared__ float s_red[2 * 2 * FINF];
    __shared__ int s_b0;
    int tid = threadIdx.x;
    int n0 = blockIdx.x * 256;
    int n = n0 + tid;
    if (tid < 2 * 2 * FINF) s_red[tid] = 0.f;
    if (tid == 0) s_b0 = batch[n0 < NN ? n0 : (NN - 1)];
    __syncthreads();

    if (n < NN) {
        int b = batch[n];
        float f = 1.0f / g_nn[b];
        float xv[16];
        {
            float4 t0 = x4[n * 4 + 0], t1 = x4[n * 4 + 1], t2 = x4[n * 4 + 2], t3 = x4[n * 4 + 3];
            xv[0] = t0.x; xv[1] = t0.y; xv[2] = t0.z; xv[3] = t0.w;
            xv[4] = t1.x; xv[5] = t1.y; xv[6] = t1.z; xv[7] = t1.w;
            xv[8] = t2.x; xv[9] = t2.y; xv[10] = t2.z; xv[11] = t2.w;
            xv[12] = t3.x; xv[13] = t3.y; xv[14] = t3.z; xv[15] = t3.w;
        }
        int e = g_diag[n];
        float4 de = (e >= 0) ? attr[e] : make_float4(0.f, 0.f, 0.f, 0.f);
        float4 rr = g_rows[n];
        float4 cc = g_cols[n];

        float feat[KF];
#pragma unroll
        for (int j = 0; j < 16; j++) feat[j] = xv[j];
#pragma unroll
        for (int j = 0; j < 16; j++) feat[16 + j] = xv[j] * f;
        feat[32] = de.x; feat[33] = de.y; feat[34] = de.z; feat[35] = de.w;
        feat[36] = rr.x * f; feat[37] = rr.y * f; feat[38] = rr.z * f; feat[39] = rr.w * f;
        feat[40] = cc.x * f; feat[41] = cc.y * f; feat[42] = cc.z * f; feat[43] = cc.w * f;

        __nv_bfloat16 row[ROWW];
#pragma unroll
        for (int j = 0; j < ROWW; j++) row[j] = __float2bfloat16(0.f);
#pragma unroll
        for (int j = 0; j < KF; j++) {
            float v = feat[j];
            __nv_bfloat16 h = __float2bfloat16(v);
            row[j] = h;
            row[48 + j] = __float2bfloat16(v - __bfloat162float(h));
        }
        uint4* dst = (uint4*)&g_A2[(size_t)n * ROWW];
        const uint4* src = (const uint4*)row;
#pragma unroll
        for (int t = 0; t < 12; t++) dst[t] = src[t];

        int gi = (b != s_b0) ? 1 : 0;
        float* sr = &s_red[gi * 2 * FINF];
#pragma unroll
        for (int j = 0; j < 16; j++) atomicAdd(&sr[j], feat[j]);
        atomicAdd(&sr[16], de.x); atomicAdd(&sr[17], de.y);
        atomicAdd(&sr[18], de.z); atomicAdd(&sr[19], de.w);
#pragma unroll
        for (int j = 0; j < 16; j++) atomicAdd(&sr[FINF + j], feat[16 + j]);
        atomicAdd(&sr[FINF + 16], feat[40]); atomicAdd(&sr[FINF + 17], feat[41]);
        atomicAdd(&sr[FINF + 18], feat[42]); atomicAdd(&sr[FINF + 19], feat[43]);
    }
    __syncthreads();
    if (tid < 2 * 2 * FINF) {
        int gi = tid / (2 * FINF);
        int j = tid - gi * (2 * FINF);
        int b = s_b0 + gi;
        float v = s_red[tid];
        if (b < BB && v != 0.f) {
            if (j < FINF) atomicAdd(&g_sdp[b * FINF + j], v);
            else          atomicAdd(&g_sa[b * FINF + (j - FINF)], v);
        }
    }
}

// ---------------- K4: per-graph constant ----------------
__global__ void k_c(const float* __restrict__ ke, const float* __restrict__ be) {
    int i = blockIdx.x * blockDim.x + threadIdx.x;
    if (i >= BB * NCOL) return;
    int b = i / NCOL, col = i - b * NCOL;
    int m = col >> 5, h = col & 31;
    float fb = 1.0f / g_nn[b];
    float fb2 = fb * fb;
    const float* k1 = ke + ((m * 5 + 1) * HH + h) * FINF;
    const float* k4 = ke + ((m * 5 + 4) * HH + h) * FINF;
    float acc = be[col];
#pragma unroll
    for (int f = 0; f < FINF; f++)
        acc += k1[f] * (g_sdp[b * FINF + f] * fb) + k4[f] * (g_sa[b * FINF + f] * fb2);
    g_c[i] = acc;
}

// ---------------- K5: packed bf16 hi/lo folded weights ----------------
__global__ void k_w(const float* __restrict__ ke) {
    int col = blockIdx.x * blockDim.x + threadIdx.x;
    if (col >= NCOL) return;
    int m = col >> 5, h = col & 31;
    const float* k0 = ke + ((m * 5 + 0) * HH + h) * FINF;
    const float* k2 = ke + ((m * 5 + 2) * HH + h) * FINF;
    const float* k3 = ke + ((m * 5 + 3) * HH + h) * FINF;
    float wc[KF];
#pragma unroll
    for (int f = 0; f < 16; f++) wc[f] = k0[f];
#pragma unroll
    for (int f = 0; f < 16; f++) wc[16 + f] = k2[f] + k3[f];
#pragma unroll
    for (int j = 0; j < 4; j++) wc[32 + j] = k0[16 + j];
#pragma unroll
    for (int j = 0; j < 4; j++) wc[36 + j] = k2[16 + j];
#pragma unroll
    for (int j = 0; j < 4; j++) wc[40 + j] = k3[16 + j];

    __nv_bfloat16 row[ROWW];
#pragma unroll
    for (int j = 0; j < ROWW; j++) row[j] = __float2bfloat16(0.f);
#pragma unroll
    for (int j = 0; j < KF; j++) {
        float v = wc[j];
        __nv_bfloat16 hh = __float2bfloat16(v);
        row[j] = hh;
        row[48 + j] = __float2bfloat16(v - __bfloat162float(hh));
    }
    uint4* dst = (uint4*)&g_W2[(size_t)col * ROWW];
    const uint4* src = (const uint4*)row;
#pragma unroll
    for (int t = 0; t < 12; t++) dst[t] = src[t];
}

// ---------------- K6: wmma bf16 GEMM + relu + per-graph reduce ----------------
// grid (391, 16), 256 threads (8 warps). CTA tile 128 nodes x 128 cols.
// Warp tile 64x32 (warp grid 2 M x 4 N). K = 9 steps of 16 over hi/lo products.
#define ASM_OFF 0
#define BSM_OFF (128 * SMSTRIDE)                 // in bf16 elements
#define SMEM_AB_BYTES (2 * 128 * SMSTRIDE * 2)   // 57344
#define STG_OFF_BYTES SMEM_AB_BYTES              // staging after A/B
#define SMEM_DYN (SMEM_AB_BYTES + 8 * 16 * 36 * 4)  // + 18432 = 75776

__global__ void __launch_bounds__(256) k_main(const int* __restrict__ batch) {
    extern __shared__ char dsm[];
    __shared__ int s_batch[NT];
    __shared__ float sg[2 * 128];
    __shared__ int s_bfirst;

    __nv_bfloat16* Asm = (__nv_bfloat16*)dsm;
    __nv_bfloat16* Bsm = Asm + BSM_OFF;
    float* stg = (float*)(dsm + STG_OFF_BYTES);

    const int tid = threadIdx.x;
    const int wid = tid >> 5;
    const int lane = tid & 31;
    const int wm = wid >> 2;      // 0..1 : M block of 64
    const int wn = wid & 3;       // 0..3 : N block of 32
    const int nbase = blockIdx.x * NT;
    const int colbase = blockIdx.y * 128;

    if (tid < NT) {
        int n = nbase + tid;
        s_batch[tid] = batch[n < NN ? n : (NN - 1)];
    }
    if (tid == 0) s_bfirst = batch[nbase];
    for (int i = tid; i < 256; i += 256) sg[i] = 0.f;

    // load A tile (128 rows x 96 bf16) and B tile (128 cols x 96 bf16) into smem
    {
        const uint4* srcA = (const uint4*)&g_A2[(size_t)nbase * ROWW];
        const uint4* srcB = (const uint4*)&g_W2[(size_t)colbase * ROWW];
        for (int i = tid; i < 128 * 12; i += 256) {
            int r = i / 12, c = i - r * 12;
            *(uint4*)((char*)Asm + r * (SMSTRIDE * 2) + c * 16) = srcA[i];
            *(uint4*)((char*)Bsm + r * (SMSTRIDE * 2) + c * 16) = srcB[i];
        }
    }
    __syncthreads();

    wmma::fragment<wmma::accumulator, 16, 16, 16, float> cf[4][2];
#pragma unroll
    for (int i = 0; i < 4; i++)
#pragma unroll
        for (int j = 0; j < 2; j++) wmma::fill_fragment(cf[i][j], 0.f);

    const int offA[9] = {0, 16, 32, 48, 64, 80, 0, 16, 32};
    const int offB[9] = {0, 16, 32, 0, 16, 32, 48, 64, 80};
#pragma unroll
    for (int s = 0; s < 9; s++) {
        wmma::fragment<wmma::matrix_a, 16, 16, 16, __nv_bfloat16, wmma::row_major> af[4];
        wmma::fragment<wmma::matrix_b, 16, 16, 16, __nv_bfloat16, wmma::col_major> bf[2];
#pragma unroll
        for (int i = 0; i < 4; i++)
            wmma::load_matrix_sync(af[i], Asm + (wm * 64 + i * 16) * SMSTRIDE + offA[s], SMSTRIDE);
#pragma unroll
        for (int j = 0; j < 2; j++)
            wmma::load_matrix_sync(bf[j], Bsm + (wn * 32 + j * 16) * SMSTRIDE + offB[s], SMSTRIDE);
#pragma unroll
        for (int i = 0; i < 4; i++)
#pragma unroll
            for (int j = 0; j < 2; j++)
                wmma::mma_sync(cf[i][j], af[i], bf[j], cf[i][j]);
    }

    // epilogue: per-warp 16x32 slabs -> relu(z + c[b]) -> per-graph running sums
    const int bfirst = s_bfirst;
    float* st = stg + wid * (16 * 36);
    float sum = 0.f, cval = 0.f;
    int cur = -1, gi = 0;
    const int mycol = colbase + wn * 32 + lane;

#pragma unroll
    for (int i = 0; i < 4; i++) {
        wmma::store_matrix_sync(st, cf[i][0], 36, wmma::mem_row_major);
        wmma::store_matrix_sync(st + 16, cf[i][1], 36, wmma::mem_row_major);
        __syncwarp();
        int rbase = wm * 64 + i * 16;
#pragma unroll 1
        for (int r = 0; r < 16; r++) {
            int n = nbase + rbase + r;
            if (n >= NN) break;
            int b = s_batch[rbase + r];
            if (b != cur) {
                if (cur >= 0) atomicAdd(&sg[gi * 128 + wn * 32 + lane], sum);
                sum = 0.f;
                cur = b;
                gi = (b != bfirst) ? 1 : 0;
                cval = __ldg(&g_c[b * NCOL + mycol]);
            }
            sum += fmaxf(st[r * 36 + lane] + cval, 0.f);
        }
        __syncwarp();
    }
    if (cur >= 0) atomicAdd(&sg[gi * 128 + wn * 32 + lane], sum);
    __syncthreads();

    // flush per-graph partials to global
    {
        int gi2 = tid >> 7, col = tid & 127;
        int b = bfirst + gi2;
        float v = sg[tid];
        if (b < BB && v != 0.f) atomicAdd(&g_inv[b * NCOL + colbase + col], v);
    }
}

// ---------------- K7: final contraction (bias_inv cancels) ----------------
__global__ void k_out(const float* __restrict__ kinv, const float* __restrict__ be,
                      float* __restrict__ out) {
    int i = blockIdx.x * blockDim.x + threadIdx.x;
    if (i >= BB * MM) return;
    int b = i / MM, m = i - b * MM;
    float fb = 1.0f / g_nn[b];
    float s = 0.f;
#pragma unroll
    for (int h = 0; h < HH; h++) {
        float ib = g_inv[b * NCOL + m * HH + h] * fb;
        float zg = fmaxf(be[m * HH + h], 0.f);
        s += (ib - zg) * kinv[m * HH + h];
    }
    out[i] = s;
}

// ---------------- launch ----------------
extern "C" void kernel_launch(void* const* d_in, const int* in_sizes, int n_in,
                              void* d_out, int out_size) {
    const float4* x4   = (const float4*)d_in[0];
    const float4* attr = (const float4*)d_in[1];
    const float*  ke   = (const float*)d_in[2];
    const float*  kinv = (const float*)d_in[3];
    const float*  be   = (const float*)d_in[4];
    // d_in[5] = bias_inv (cancels in psi - zerograph)
    const int*    ei    = (const int*)d_in[6];
    const int*    batch = (const int*)d_in[7];
    float* out = (float*)d_out;

    cudaFuncSetAttribute(k_main, cudaFuncAttributeMaxDynamicSharedMemorySize, SMEM_DYN);

    k_zero<<<512, 256>>>();
    k_bound<<<(NN + 255) / 256, 256>>>(batch);
    k_counts<<<1, 128>>>();
    k_edge<<<(EE + 255) / 256, 256>>>(ei, attr);
    k_node<<<(NN + 255) / 256, 256>>>(x4, attr, batch);
    k_c<<<(BB * NCOL + 255) / 256, 256>>>(ke, be);
    k_w<<<(NCOL + 255) / 256, 256>>>(ke);
    dim3 grid(TILES, NCOL / 128);
    k_main<<<grid, 256, SMEM_DYN>>>(batch);
    k_out<<<(BB * MM + 255) / 256, 256>>>(kinv, be, out);
}

// round 6
// speedup vs baseline: 1.1320x; 1.1320x over previous
#include <cuda_runtime.h>
#include <cuda_bf16.h>
#include <mma.h>
#include <cstdint>

using namespace nvcuda;

// Problem constants
#define NN   50000
#define EE   1600000
#define BB   128
#define MM   64
#define HH   32
#define FINF 20
#define KF   44
#define NCOL 2048
#define ROWW 96            // bf16 per packed row: [hi 0..47 | lo 48..95]
#define RPC  1024          // rows per CTA
#define SUBT 8             // subtiles of 128 rows
#define CTAX 49            // ceil(50000/1024)
#define NROWS_PAD (CTAX * RPC)   // 50176
#define SMST 120           // smem row stride in bf16 (240B: conflict-free for LDSM)

// ---------------- device scratch ----------------
__device__ float4 g_rows[NN];
__device__ float4 g_cols[NN];
__device__ int   g_diag[NN];
__device__ int   g_end[BB];
__device__ float g_sdp[BB * FINF];
__device__ float g_sa[BB * FINF];
__device__ __nv_bfloat16 g_A2[(size_t)NROWS_PAD * ROWW];
__device__ __nv_bfloat16 g_W2[(size_t)NCOL * ROWW];
__device__ float g_inv[BB * NCOL];

__device__ __forceinline__ float inv_count(int b) {
    int st = (b == 0) ? 0 : g_end[b - 1];
    return 1.0f / (float)(g_end[b] - st);
}

// ---------------- K0: fused init (zero + boundaries + weight pack) ----------------
__global__ void k_init(const int* __restrict__ batch, const float* __restrict__ ke) {
    int i = blockIdx.x * blockDim.x + threadIdx.x;
    int stride = gridDim.x * blockDim.x;
    float4 z4 = make_float4(0.f, 0.f, 0.f, 0.f);
    for (int j = i; j < NN; j += stride) { g_rows[j] = z4; g_cols[j] = z4; g_diag[j] = -1; }
    for (int j = i; j < BB * FINF; j += stride) { g_sdp[j] = 0.f; g_sa[j] = 0.f; }
    for (int j = i; j < BB * NCOL; j += stride) g_inv[j] = 0.f;
    const int padN = (NROWS_PAD - NN) * ROWW;
    __nv_bfloat16 zb = __float2bfloat16(0.f);
    for (int j = i; j < padN; j += stride) g_A2[(size_t)NN * ROWW + j] = zb;
    // segment boundaries (sorted batch, every graph non-empty)
    for (int n = i; n < NN; n += stride) {
        int b = batch[n];
        int nb = (n + 1 < NN) ? batch[n + 1] : BB;
        if (nb != b) g_end[b] = n + 1;
    }
    // pack folded hi/lo bf16 weights
    for (int col = i; col < NCOL; col += stride) {
        int m = col >> 5, h = col & 31;
        const float* k0 = ke + ((m * 5 + 0) * HH + h) * FINF;
        const float* k2 = ke + ((m * 5 + 2) * HH + h) * FINF;
        const float* k3 = ke + ((m * 5 + 3) * HH + h) * FINF;
        float wc[KF];
#pragma unroll
        for (int f = 0; f < 16; f++) wc[f] = k0[f];
#pragma unroll
        for (int f = 0; f < 16; f++) wc[16 + f] = k2[f] + k3[f];
#pragma unroll
        for (int j = 0; j < 4; j++) wc[32 + j] = k0[16 + j];
#pragma unroll
        for (int j = 0; j < 4; j++) wc[36 + j] = k2[16 + j];
#pragma unroll
        for (int j = 0; j < 4; j++) wc[40 + j] = k3[16 + j];
        __nv_bfloat16 row[ROWW];
#pragma unroll
        for (int j = 0; j < ROWW; j++) row[j] = __float2bfloat16(0.f);
#pragma unroll
        for (int j = 0; j < KF; j++) {
            float v = wc[j];
            __nv_bfloat16 hh = __float2bfloat16(v);
            row[j] = hh;
            row[48 + j] = __float2bfloat16(v - __bfloat162float(hh));
        }
        uint4* dst = (uint4*)&g_W2[(size_t)col * ROWW];
        const uint4* src = (const uint4*)row;
#pragma unroll
        for (int t = 0; t < 12; t++) dst[t] = src[t];
    }
}

// ---------------- K1: edge pass ----------------
__global__ void k_edge(const int* __restrict__ ei, const float4* __restrict__ attr) {
    int e = blockIdx.x * blockDim.x + threadIdx.x;
    if (e >= EE) return;
    int s = __ldg(&ei[e]);
    int d = __ldg(&ei[EE + e]);
    float4 a = attr[e];
    atomicAdd(&g_rows[s], a);
    atomicAdd(&g_cols[d], a);
    if (s == d) atomicMax(&g_diag[s], e);
}

// ---------------- K2: packed bf16 hi/lo features + per-graph sums ----------------
__global__ void __launch_bounds__(256) k_node(const float4* __restrict__ x4,
                                              const float4* __restrict__ attr,
                                              const int* __restrict__ batch) {
    __shared__ float s_red[2 * 2 * FINF];
    __shared__ int s_b0;
    int tid = threadIdx.x;
    int n0 = blockIdx.x * 256;
    int n = n0 + tid;
    if (tid < 2 * 2 * FINF) s_red[tid] = 0.f;
    if (tid == 0) s_b0 = batch[n0 < NN ? n0 : (NN - 1)];
    __syncthreads();

    if (n < NN) {
        int b = batch[n];
        float f = inv_count(b);
        float xv[16];
        {
            float4 t0 = x4[n * 4 + 0], t1 = x4[n * 4 + 1], t2 = x4[n * 4 + 2], t3 = x4[n * 4 + 3];
            xv[0] = t0.x; xv[1] = t0.y; xv[2] = t0.z; xv[3] = t0.w;
            xv[4] = t1.x; xv[5] = t1.y; xv[6] = t1.z; xv[7] = t1.w;
            xv[8] = t2.x; xv[9] = t2.y; xv[10] = t2.z; xv[11] = t2.w;
            xv[12] = t3.x; xv[13] = t3.y; xv[14] = t3.z; xv[15] = t3.w;
        }
        int e = g_diag[n];
        float4 de = (e >= 0) ? attr[e] : make_float4(0.f, 0.f, 0.f, 0.f);
        float4 rr = g_rows[n];
        float4 cc = g_cols[n];

        float feat[KF];
#pragma unroll
        for (int j = 0; j < 16; j++) feat[j] = xv[j];
#pragma unroll
        for (int j = 0; j < 16; j++) feat[16 + j] = xv[j] * f;
        feat[32] = de.x; feat[33] = de.y; feat[34] = de.z; feat[35] = de.w;
        feat[36] = rr.x * f; feat[37] = rr.y * f; feat[38] = rr.z * f; feat[39] = rr.w * f;
        feat[40] = cc.x * f; feat[41] = cc.y * f; feat[42] = cc.z * f; feat[43] = cc.w * f;

        __nv_bfloat16 row[ROWW];
#pragma unroll
        for (int j = 0; j < ROWW; j++) row[j] = __float2bfloat16(0.f);
#pragma unroll
        for (int j = 0; j < KF; j++) {
            float v = feat[j];
            __nv_bfloat16 h = __float2bfloat16(v);
            row[j] = h;
            row[48 + j] = __float2bfloat16(v - __bfloat162float(h));
        }
        uint4* dst = (uint4*)&g_A2[(size_t)n * ROWW];
        const uint4* src = (const uint4*)row;
#pragma unroll
        for (int t = 0; t < 12; t++) dst[t] = src[t];

        int gi = (b != s_b0) ? 1 : 0;
        float* sr = &s_red[gi * 2 * FINF];
#pragma unroll
        for (int j = 0; j < 16; j++) atomicAdd(&sr[j], feat[j]);
        atomicAdd(&sr[16], de.x); atomicAdd(&sr[17], de.y);
        atomicAdd(&sr[18], de.z); atomicAdd(&sr[19], de.w);
#pragma unroll
        for (int j = 0; j < 16; j++) atomicAdd(&sr[FINF + j], feat[16 + j]);
        atomicAdd(&sr[FINF + 16], feat[40]); atomicAdd(&sr[FINF + 17], feat[41]);
        atomicAdd(&sr[FINF + 18], feat[42]); atomicAdd(&sr[FINF + 19], feat[43]);
    }
    __syncthreads();
    if (tid < 2 * 2 * FINF) {
        int gi = tid / (2 * FINF);
        int j = tid - gi * (2 * FINF);
        int b = s_b0 + gi;
        float v = s_red[tid];
        if (b < BB && v != 0.f) {
            if (j < FINF) atomicAdd(&g_sdp[b * FINF + j], v);
            else          atomicAdd(&g_sa[b * FINF + (j - FINF)], v);
        }
    }
}

// ---------------- K3: wmma bf16 GEMM + relu + per-graph reduce ----------------
// grid (49, 16), 256 thr (8 warps). CTA: 1024 rows x 128 cols, B resident, 8 A-subtiles.
// Warp tile 64x32 (2 M-warps x 4 N-warps). K = 9 steps of 16 (hi/lo split products).
#define A_BYTES (128 * SMST * 2)   // 30720
#define SMEM_DYN (2 * A_BYTES + 8 * 16 * 36 * 4)   // A + B + stage = 79872

__global__ void __launch_bounds__(256, 2) k_main(const int* __restrict__ batch,
                                                 const float* __restrict__ ke,
                                                 const float* __restrict__ be) {
    extern __shared__ char dsm[];
    __nv_bfloat16* Asm = (__nv_bfloat16*)dsm;
    __nv_bfloat16* Bsm = (__nv_bfloat16*)(dsm + A_BYTES);
    float* stg = (float*)(dsm + 2 * A_BYTES);
    __shared__ int s_batch[RPC];
    __shared__ float sg[4 * 128];
    __shared__ float c_sm[4 * 128];

    const int tid = threadIdx.x;
    const int wid = tid >> 5;
    const int lane = tid & 31;
    const int wm = wid >> 2;      // 0..1
    const int wn = wid & 3;       // 0..3
    const int nbase = blockIdx.x * RPC;
    const int colbase = blockIdx.y * 128;
    const int bfirst = __ldg(&batch[nbase]);

    for (int i = tid; i < RPC; i += 256) {
        int n = nbase + i;
        s_batch[i] = __ldg(&batch[n < NN ? n : (NN - 1)]);
    }
    for (int i = tid; i < 512; i += 256) sg[i] = 0.f;

    // B tile (resident): 128 cols x 96 bf16 -> stride SMST
    {
        const uint4* srcB = (const uint4*)&g_W2[(size_t)colbase * ROWW];
        for (int i = tid; i < 128 * 12; i += 256) {
            int r = i / 12, c = i - r * 12;
            *(uint4*)((char*)Bsm + r * (SMST * 2) + c * 16) = srcB[i];
        }
    }
    // per-graph constants c[b, col] for graphs bfirst..bfirst+3 (<=4 per 1024 rows)
    for (int i = tid; i < 512; i += 256) {
        int g = i >> 7, col = i & 127;
        int b = bfirst + g;
        float v = 0.f;
        if (b < BB) {
            float fb = inv_count(b);
            float fb2 = fb * fb;
            int colG = colbase + col;
            int m = colG >> 5, h = colG & 31;
            const float* k1 = ke + ((m * 5 + 1) * HH + h) * FINF;
            const float* k4 = ke + ((m * 5 + 4) * HH + h) * FINF;
            float acc = __ldg(&be[colG]);
#pragma unroll
            for (int f = 0; f < FINF; f++)
                acc += __ldg(&k1[f]) * (g_sdp[b * FINF + f] * fb)
                     + __ldg(&k4[f]) * (g_sa[b * FINF + f] * fb2);
            v = acc;
        }
        c_sm[i] = v;
    }

    const int offA[9] = {0, 16, 32, 48, 64, 80, 0, 16, 32};
    const int offB[9] = {0, 16, 32, 0, 16, 32, 48, 64, 80};

    float sum = 0.f, cval = 0.f;
    int cur = -1;
    float* st = stg + wid * (16 * 36);

    for (int sub = 0; sub < SUBT; sub++) {
        __syncthreads();   // prior subtile reads done; also fences B/c_sm/s_batch on sub=0
        {
            const uint4* srcA = (const uint4*)&g_A2[(size_t)(nbase + sub * 128) * ROWW];
            for (int i = tid; i < 128 * 12; i += 256) {
                int r = i / 12, c = i - r * 12;
                *(uint4*)((char*)Asm + r * (SMST * 2) + c * 16) = srcA[i];
            }
        }
        __syncthreads();

        wmma::fragment<wmma::accumulator, 16, 16, 16, float> cf[4][2];
#pragma unroll
        for (int i = 0; i < 4; i++)
#pragma unroll
            for (int j = 0; j < 2; j++) wmma::fill_fragment(cf[i][j], 0.f);

#pragma unroll
        for (int s = 0; s < 9; s++) {
            wmma::fragment<wmma::matrix_a, 16, 16, 16, __nv_bfloat16, wmma::row_major> af[4];
            wmma::fragment<wmma::matrix_b, 16, 16, 16, __nv_bfloat16, wmma::col_major> bf[2];
#pragma unroll
            for (int i = 0; i < 4; i++)
                wmma::load_matrix_sync(af[i], Asm + (wm * 64 + i * 16) * SMST + offA[s], SMST);
#pragma unroll
            for (int j = 0; j < 2; j++)
                wmma::load_matrix_sync(bf[j], Bsm + (wn * 32 + j * 16) * SMST + offB[s], SMST);
#pragma unroll
            for (int i = 0; i < 4; i++)
#pragma unroll
                for (int j = 0; j < 2; j++)
                    wmma::mma_sync(cf[i][j], af[i], bf[j], cf[i][j]);
        }

        // epilogue: per-warp 16x32 slabs -> relu(z + c[b]) -> running per-graph sums
#pragma unroll
        for (int i4 = 0; i4 < 4; i4++) {
            wmma::store_matrix_sync(st, cf[i4][0], 36, wmma::mem_row_major);
            wmma::store_matrix_sync(st + 16, cf[i4][1], 36, wmma::mem_row_major);
            __syncwarp();
            int rbase = sub * 128 + wm * 64 + i4 * 16;
#pragma unroll 1
            for (int r = 0; r < 16; r++) {
                int gr = rbase + r;
                if (nbase + gr >= NN) break;
                int b = s_batch[gr];
                if (b != cur) {
                    if (cur >= 0) atomicAdd(&sg[(cur - bfirst) * 128 + wn * 32 + lane], sum);
                    sum = 0.f;
                    cur = b;
                    cval = c_sm[(b - bfirst) * 128 + wn * 32 + lane];
                }
                sum += fmaxf(st[r * 36 + lane] + cval, 0.f);
            }
            __syncwarp();
        }
    }
    if (cur >= 0) atomicAdd(&sg[(cur - bfirst) * 128 + wn * 32 + lane], sum);
    __syncthreads();

    for (int i = tid; i < 512; i += 256) {
        int g = i >> 7, col = i & 127;
        int b = bfirst + g;
        float v = sg[i];
        if (b < BB && v != 0.f) atomicAdd(&g_inv[b * NCOL + colbase + col], v);
    }
}

// ---------------- K4: final contraction (bias_inv cancels) ----------------
__global__ void k_out(const float* __restrict__ kinv, const float* __restrict__ be,
                      float* __restrict__ out) {
    int i = blockIdx.x * blockDim.x + threadIdx.x;
    if (i >= BB * MM) return;
    int b = i / MM, m = i - b * MM;
    float fb = inv_count(b);
    float s = 0.f;
#pragma unroll
    for (int h = 0; h < HH; h++) {
        float ib = g_inv[b * NCOL + m * HH + h] * fb;
        float zg = fmaxf(be[m * HH + h], 0.f);
        s += (ib - zg) * kinv[m * HH + h];
    }
    out[i] = s;
}

// ---------------- launch ----------------
extern "C" void kernel_launch(void* const* d_in, const int* in_sizes, int n_in,
                              void* d_out, int out_size) {
    const float4* x4   = (const float4*)d_in[0];
    const float4* attr = (const float4*)d_in[1];
    const float*  ke   = (const float*)d_in[2];
    const float*  kinv = (const float*)d_in[3];
    const float*  be   = (const float*)d_in[4];
    // d_in[5] = bias_inv (cancels in psi - zerograph)
    const int*    ei    = (const int*)d_in[6];
    const int*    batch = (const int*)d_in[7];
    float* out = (float*)d_out;

    cudaFuncSetAttribute(k_main, cudaFuncAttributeMaxDynamicSharedMemorySize, SMEM_DYN);

    k_init<<<512, 256>>>(batch, ke);                    // launch 0
    k_edge<<<(EE + 255) / 256, 256>>>(ei, attr);        // launch 1
    k_node<<<(NN + 255) / 256, 256>>>(x4, attr, batch); // launch 2
    dim3 grid(CTAX, NCOL / 128);
    k_main<<<grid, 256, SMEM_DYN>>>(batch, ke, be);     // launch 3 (profiled)
    k_out<<<(BB * MM + 255) / 256, 256>>>(kinv, be, out); // launch 4
}